// round 17
// baseline (speedup 1.0000x reference)
#include <cuda_runtime.h>
#include <cuda_bf16.h>

// Weighted cross-entropy, one row per block + fire-and-forget fused reduction.
//   loss[i] = log(sum_j exp(logits[i,j])) - logits[i, label[i]]
//   w[i]    = 1 - bias_probs[i, label[i]]
//   out     = sum(w*loss) / sum(w)
//
// Structure rules learned R12-R16:
//  - NO barrier waits on thread 0's label/gather chain (costs ~10us).
//  - NOTHING latency-bound between block reduce and CTA retirement: the
//    R13/14/16 fused exits all lost ~10us because a __syncthreads waited on
//    an atomic ROUND-TRIP. Here row blocks use red.add.release (no return,
//    no wait) and retire exactly like the fastest two-kernel version.
//  - Final reduction runs in a dedicated poller block (blockIdx == N,
//    scheduled in the last wave) that spins on the counter, then reduces the
//    L2-hot partials. Deterministic: fixed-order sums only.
//  - Streaming loop unrolled x2 (two independent LDG.128 in flight):
//    64 warps x 1 load was latency-limited to ~85% DRAM.

#define MAX_ROWS 16384

__device__ float2 g_partial[MAX_ROWS];    // (w*loss, w) per row
__device__ unsigned int g_count = 0;

__inline__ __device__ float warp_sum(float v) {
    #pragma unroll
    for (int o = 16; o > 0; o >>= 1) v += __shfl_down_sync(0xffffffffu, v, o);
    return v;
}

__global__ void __launch_bounds__(256)
rw_fused_kernel(const float* __restrict__ logits,
                const float* __restrict__ bias,
                const int*   __restrict__ lab32,   // raw label words (i32 view)
                float*       __restrict__ out,
                int V, int N)
{
    const int row = blockIdx.x;

    // ---------------- poller block: final reduction ----------------
    if (row == N) {
        if (threadIdx.x == 0) {
            unsigned int c;
            do {
                asm volatile("ld.acquire.gpu.u32 %0, [%1];"
                             : "=r"(c) : "l"(&g_count) : "memory");
                if (c < (unsigned int)N) __nanosleep(200);
            } while (c < (unsigned int)N);
        }
        __syncthreads();

        __shared__ float s_wl[8], s_w[8];
        float wl = 0.f, ww = 0.f;
        if ((N & 1) == 0) {
            const float4* p4 = reinterpret_cast<const float4*>(g_partial);
            const int n4 = N >> 1;                 // 2 pairs per float4
            #pragma unroll 4
            for (int i = threadIdx.x; i < n4; i += 256) {
                const float4 p = __ldcg(&p4[i]);
                wl += p.x + p.z;
                ww += p.y + p.w;
            }
        } else {
            for (int i = threadIdx.x; i < N; i += 256) {
                const float2 p = __ldcg(&g_partial[i]);
                wl += p.x;
                ww += p.y;
            }
        }
        wl = warp_sum(wl);
        ww = warp_sum(ww);
        if ((threadIdx.x & 31) == 0) {
            s_wl[threadIdx.x >> 5] = wl;
            s_w [threadIdx.x >> 5] = ww;
        }
        __syncthreads();
        if (threadIdx.x == 0) {
            float twl = 0.f, tw = 0.f;
            #pragma unroll
            for (int k = 0; k < 8; k++) { twl += s_wl[k]; tw += s_w[k]; }
            out[0] = twl / tw;
            g_count = 0;                           // reset for next graph replay
        }
        return;
    }

    // ---------------- row blocks: streaming logsumexp ----------------
    __shared__ float s_red[8];

    // Thread 0 only, registers, no barrier involvement: dtype detect
    // (int64 LE with values < V => odd words of first 32 labels all zero;
    // for random int32 the chance is ~(1/32000)^32) + label gather chain.
    // Issued here, consumed at the tail — latency hidden under the stream.
    float xl = 0.f, w = 0.f;
    if (threadIdx.x == 0) {
        int is64 = 1;
        #pragma unroll
        for (int j = 1; j < 64; j += 2)
            if (lab32[j] != 0) is64 = 0;
        const int lbl = is64 ? lab32[2 * row] : lab32[row];
        const size_t idx = (size_t)row * V + (size_t)lbl;
        xl = logits[idx];
        w  = 1.0f - bias[idx];
    }

    const float4* rp = reinterpret_cast<const float4*>(logits + (size_t)row * V);
    const int nv4 = V >> 2;

    float a0 = 0.f, a1 = 0.f, a2 = 0.f, a3 = 0.f;
    int i = threadIdx.x;
    // Unroll x2: two independent LDG.128 in flight per warp (MLP 2).
    for (; i + 256 < nv4; i += 512) {
        const float4 u = __ldcs(&rp[i]);
        const float4 v = __ldcs(&rp[i + 256]);
        a0 += __expf(u.x) + __expf(v.x);
        a1 += __expf(u.y) + __expf(v.y);
        a2 += __expf(u.z) + __expf(v.z);
        a3 += __expf(u.w) + __expf(v.w);
    }
    if (i < nv4) {
        const float4 u = __ldcs(&rp[i]);
        a0 += __expf(u.x);
        a1 += __expf(u.y);
        a2 += __expf(u.z);
        a3 += __expf(u.w);
    }
    float s = (a0 + a1) + (a2 + a3);

    // tail safety (V=32000 divisible by 4; keeps kernel shape-generic)
    for (int t = (nv4 << 2) + threadIdx.x; t < V; t += 256)
        s += __expf(__ldcs(&logits[(size_t)row * V + t]));

    s = warp_sum(s);
    if ((threadIdx.x & 31) == 0) s_red[threadIdx.x >> 5] = s;
    __syncthreads();

    if (threadIdx.x == 0) {
        float t = 0.f;
        #pragma unroll
        for (int k = 0; k < 8; k++) t += s_red[k];
        const float loss = logf(t) - xl;
        g_partial[row] = make_float2(w * loss, w);
        // Fire-and-forget release increment: orders the store above, returns
        // nothing, blocks retirement on nothing.
        asm volatile("red.add.release.gpu.u32 [%0], %1;"
                     :: "l"(&g_count), "r"(1u) : "memory");
    }
}

extern "C" void kernel_launch(void* const* d_in, const int* in_sizes, int n_in,
                              void* d_out, int out_size)
{
    const float* logits = (const float*)d_in[0];
    const float* bias   = (const float*)d_in[1];
    const int*   lab32  = (const int*)  d_in[2];
    float*       out    = (float*)d_out;

    const int N = in_sizes[2];                      // rows = label count
    const int V = (int)((long long)in_sizes[0] / N);

    rw_fused_kernel<<<N + 1, 256>>>(logits, bias, lab32, out, V, N);
}